// round 14
// baseline (speedup 1.0000x reference)
#include <cuda_runtime.h>
#include <math.h>
#include <stdint.h>

#define NE   100000
#define NR   200
#define EE   500000
#define IND  128
#define OUTD 200
#define KK   384      // 128 ent_s | 128 P2(rel) | 128 P3(obj)
#define JP   208      // padded Wfull width

// ---------------- scratch ----------------
__device__ float g_ent_rn[NE * IND];
__device__ float g_rel_rn[NR * IND];
__device__ float g_d1[NE];
__device__ float g_d3[NE];
__device__ float g_d2[NR];
__device__ float g_weff[385];
__device__ float g_Wfull[KK * JP];        // [k][j], tf32-rounded, zero-padded j>=200
__device__ float g_eb[EE];
__device__ int   g_histS[NE];
__device__ int   g_offS[NE];
__device__ int   g_curS[NE];
__device__ int   g_histR[NR];
__device__ int   g_offR[NR];
__device__ int   g_curR[NR];
__device__ int   g_bsum[128];
__device__ int   g_boff[128];
__device__ unsigned int g_sRO[EE];        // s-sorted: (r<<17)|o
__device__ float g_sEb[EE];
__device__ int   g_rS[EE];                // r-sorted
__device__ int   g_rO[EE];
__device__ float g_rE[EE];
__device__ float g_S1[NR * IND];
__device__ float g_S2[NR * IND];
__device__ float g_ebr[NR];

// ---------------- helpers ----------------
__device__ __forceinline__ uint32_t smem_u32(const void* p) {
    uint32_t a;
    asm("{ .reg .u64 t; cvta.to.shared.u64 t, %1; cvt.u32.u64 %0, t; }"
        : "=r"(a) : "l"(p));
    return a;
}
__device__ __forceinline__ float to_tf32(float x) {
    uint32_t u;
    asm("cvt.rna.tf32.f32 %0, %1;" : "=r"(u) : "f"(x));
    return __uint_as_float(u);
}
__device__ __forceinline__ void mma_tf32(float* c, const uint32_t* a, const uint32_t* b) {
    asm volatile(
        "mma.sync.aligned.m16n8k8.row.col.f32.tf32.tf32.f32 "
        "{%0,%1,%2,%3}, {%4,%5,%6,%7}, {%8,%9}, {%0,%1,%2,%3};"
        : "+f"(c[0]), "+f"(c[1]), "+f"(c[2]), "+f"(c[3])
        : "r"(a[0]), "r"(a[1]), "r"(a[2]), "r"(a[3]), "r"(b[0]), "r"(b[1]));
}
__device__ __forceinline__ float warp_sum(float v) {
    #pragma unroll
    for (int off = 16; off >= 1; off >>= 1) v += __shfl_xor_sync(0xffffffffu, v, off);
    return v;
}

// ---------------- zero small scratch ----------------
__global__ void kz() {
    int i = (int)blockIdx.x * blockDim.x + threadIdx.x;
    if (i < NE) g_histS[i] = 0;
    if (i < NR) { g_histR[i] = 0; g_ebr[i] = 0.f; }
    if (i < NR * IND) { g_S1[i] = 0.f; g_S2[i] = 0.f; }
}

// ---------------- w_eff = Wa2 @ Wa ; bias_eff ----------------
__global__ void kw(const float* __restrict__ Wa, const float* __restrict__ ba,
                   const float* __restrict__ Wa2, const float* __restrict__ ba2) {
    int k = threadIdx.x;
    if (k < 384) {
        float acc = 0.f;
        for (int j = 0; j < OUTD; j++) acc += Wa2[j] * Wa[j * 384 + k];
        g_weff[k] = acc;
    } else if (k == 384) {
        float acc = ba2[0];
        for (int j = 0; j < OUTD; j++) acc += Wa2[j] * ba[j];
        g_weff[384] = acc;
    }
}

// ---------------- renorm + per-row dots (tf32-rounded stores) ----------------
__global__ void krn_ent(const float* __restrict__ ent) {
    int w    = ((int)blockIdx.x * blockDim.x + threadIdx.x) >> 5;
    int lane = threadIdx.x & 31;
    if (w >= NE) return;
    float4 v = *(const float4*)&ent[(long)w * IND + lane * 4];
    float ss = warp_sum(v.x * v.x + v.y * v.y + v.z * v.z + v.w * v.w);
    float sc = fminf(1.f, 1.f / fmaxf(sqrtf(ss), 1e-12f));
    float4 r = make_float4(to_tf32(v.x * sc), to_tf32(v.y * sc),
                           to_tf32(v.z * sc), to_tf32(v.w * sc));
    *(float4*)&g_ent_rn[(long)w * IND + lane * 4] = r;
    float4 w1 = *(const float4*)&g_weff[lane * 4];
    float4 w3 = *(const float4*)&g_weff[256 + lane * 4];
    float a1 = warp_sum(r.x * w1.x + r.y * w1.y + r.z * w1.z + r.w * w1.w);
    float a3 = warp_sum(r.x * w3.x + r.y * w3.y + r.z * w3.z + r.w * w3.w);
    if (lane == 0) { g_d1[w] = a1; g_d3[w] = a3; }
}

__global__ void krn_rel(const float* __restrict__ rel) {
    int w    = ((int)blockIdx.x * blockDim.x + threadIdx.x) >> 5;
    int lane = threadIdx.x & 31;
    if (w >= NR) return;
    float4 v = *(const float4*)&rel[(long)w * IND + lane * 4];
    float ss = warp_sum(v.x * v.x + v.y * v.y + v.z * v.z + v.w * v.w);
    float sc = fminf(1.f, 1.f / fmaxf(sqrtf(ss), 1e-12f));
    float4 r = make_float4(to_tf32(v.x * sc), to_tf32(v.y * sc),
                           to_tf32(v.z * sc), to_tf32(v.w * sc));
    *(float4*)&g_rel_rn[(long)w * IND + lane * 4] = r;
    float4 w2 = *(const float4*)&g_weff[128 + lane * 4];
    float a2 = warp_sum(r.x * w2.x + r.y * w2.y + r.z * w2.z + r.w * w2.w);
    if (lane == 0) g_d2[w] = a2;
}

// ---------------- Wfull[384][208] = Wa^T, tf32-rounded, zero pad ----------------
__global__ void kwf(const float* __restrict__ Wa) {
    int idx = (int)blockIdx.x * blockDim.x + threadIdx.x;
    if (idx >= KK * JP) return;
    int k = idx / JP, j = idx % JP;
    g_Wfull[idx] = (j < OUTD) ? to_tf32(Wa[(long)j * KK + k]) : 0.f;
}

// ---------------- per-edge: e_b + histograms ----------------
__global__ void kedge(const int* __restrict__ trip) {
    int e = (int)blockIdx.x * blockDim.x + threadIdx.x;
    if (e >= EE) return;
    int s = trip[3 * e], r = trip[3 * e + 1], o = trip[3 * e + 2];
    float x  = g_d1[s] + g_d2[r] + g_d3[o] + g_weff[384];
    float lr = x >= 0.f ? x : 0.01f * x;
    float eb = expf(-lr);
    g_eb[e] = eb;
    atomicAdd(&g_histS[s], 1);
    atomicAdd(&g_histR[r], 1);
}

// ---------------- scans ----------------
__global__ void scanA() {
    __shared__ int sh[1024];
    int b = blockIdx.x, t = threadIdx.x;
    int i = b * 1024 + t;
    int v = (i < NE) ? g_histS[i] : 0;
    int x = v;
    sh[t] = x; __syncthreads();
    #pragma unroll
    for (int off = 1; off < 1024; off <<= 1) {
        int y = (t >= off) ? sh[t - off] : 0;
        __syncthreads();
        x += y; sh[t] = x;
        __syncthreads();
    }
    if (i < NE) g_offS[i] = x - v;
    if (t == 1023) g_bsum[b] = x;
}
__global__ void scanBR() {
    if (blockIdx.x == 0 && threadIdx.x == 0) {
        int acc = 0;
        for (int b = 0; b < 98; b++) { g_boff[b] = acc; acc += g_bsum[b]; }
    }
    if (blockIdx.x == 0 && threadIdx.x == 1) {
        int acc = 0;
        for (int r = 0; r < NR; r++) { g_offR[r] = acc; g_curR[r] = acc; acc += g_histR[r]; }
    }
}
__global__ void scanC() {
    int i = (int)blockIdx.x * blockDim.x + threadIdx.x;
    if (i < NE) {
        int o = g_offS[i] + g_boff[blockIdx.x];
        g_offS[i] = o;
        g_curS[i] = o;
    }
}

// ---------------- scatter edges by s and by r ----------------
__global__ void kscatter(const int* __restrict__ trip) {
    int e = (int)blockIdx.x * blockDim.x + threadIdx.x;
    if (e >= EE) return;
    int s = trip[3 * e], r = trip[3 * e + 1], o = trip[3 * e + 2];
    float eb = g_eb[e];
    int ps = atomicAdd(&g_curS[s], 1);
    g_sRO[ps] = ((unsigned int)r << 17) | (unsigned int)o;
    g_sEb[ps] = eb;
    int pr = atomicAdd(&g_curR[r], 1);
    g_rS[pr] = s; g_rO[pr] = o; g_rE[pr] = eb;
}

// ---------------- relation sums ----------------
__global__ void kr() {
    int r = blockIdx.x;
    int chunk = blockIdx.y;
    int t = threadIdx.x;
    int d = t & 127;
    bool lo = t < 128;
    int base = g_offR[r], cnt = g_histR[r];
    int c0 = base + (int)((long)chunk * cnt / 8);
    int c1 = base + (int)((long)(chunk + 1) * cnt / 8);
    if (c1 <= c0) return;
    float acc = 0.f, ebsum = 0.f;
    #pragma unroll 4
    for (int i = c0; i < c1; i++) {
        float e = g_rE[i];
        int node = lo ? g_rS[i] : g_rO[i];
        acc += e * g_ent_rn[(long)node * IND + d];
        ebsum += e;
    }
    atomicAdd(lo ? &g_S1[r * IND + d] : &g_S2[r * IND + d], acc);
    if (t == 0) atomicAdd(&g_ebr[r], ebsum);
}

// ================= fused: node aggregation + tf32 GEMM =================
// Block = 64 rows. X smem [64][388]: cols 0..127 ent_rn (cp.async, FULL 128 cols:
// 2048 float4), 128..255 = P2, 256..383 = P3 (register-accumulated, tf32-rounded).
// Then full-width 208-col tf32 mma off the smem X-tile.
// smem low: bias[208] @ 0..831, msk[64] @ 896..1151, X @ 1280.
#define BM   64
#define XS   388                       // X row stride (floats); 388%32=4 -> conflict-free frags
#define BP   216                       // B row stride; 216%32=24 -> conflict-free
#define X_BYTES   (BM * XS * 4)        // 99328
#define B_BUF_BYTES (32 * BP * 4)      // 27648
#define SOFF_MSK  896
#define SOFF_X    1280
#define SOFF_B    (SOFF_X + X_BYTES)
#define SMEM_FUSE (SOFF_B + 2 * B_BUF_BYTES)   // 155904 B
#define B_F4_PER_CHUNK (32 * 52)       // 1664 float4 transfers per B chunk

__global__ void __launch_bounds__(256) kfuse(const float* __restrict__ ba,
                                             float* __restrict__ out) {
    extern __shared__ __align__(128) char sm[];
    uint32_t sb = smem_u32(sm);
    float* bias = (float*)sm;                  // floats 0..207
    float* msk  = (float*)(sm + SOFF_MSK);     // 64 floats
    int tid = threadIdx.x, wid = tid >> 5, lane = tid & 31;
    int n0 = (int)blockIdx.x * BM;

    if (tid < JP) bias[tid] = (tid < OUTD) ? ba[tid] : 0.f;

    // ---- issue cp.async: ent part of X, FULL 64x128 = 2048 float4 (group 0) ----
    #pragma unroll
    for (int it = 0; it < 8; it++) {
        int idx = tid + it * 256;              // 0..2047
        int row = idx >> 5, kq = idx & 31;     // row 0..63, kq 0..31 (float4 col)
        int n = n0 + row;
        int nc = (n < NE) ? n : (NE - 1);
        uint32_t dst = sb + SOFF_X + (uint32_t)(row * (XS * 4) + kq * 16);
        const float* src = g_ent_rn + (size_t)nc * IND + kq * 4;
        uint32_t sz = (n < NE) ? 16u : 0u;
        asm volatile("cp.async.ca.shared.global [%0], [%1], 16, %2;"
                     :: "r"(dst), "l"(src), "r"(sz));
    }
    asm volatile("cp.async.commit_group;");

    // ---- issue B chunks 0 and 1 (groups 1, 2): full 208 cols ----
    #pragma unroll
    for (int cb = 0; cb < 2; cb++) {
        uint32_t bbase = sb + SOFF_B + cb * B_BUF_BYTES;
        #pragma unroll
        for (int it = 0; it < 7; it++) {
            int idx = tid + it * 256;          // 0..1791
            if (idx < B_F4_PER_CHUNK) {
                int k = idx / 52, c4 = idx % 52;
                uint32_t dst = bbase + (uint32_t)(k * (BP * 4) + c4 * 16);
                const float* src = g_Wfull + (size_t)(cb * 32 + k) * JP + c4 * 4;
                asm volatile("cp.async.ca.shared.global [%0], [%1], 16;"
                             :: "r"(dst), "l"(src));
            }
        }
        asm volatile("cp.async.commit_group;");
    }

    // ---- phase 1: per-node edge aggregation into X cols 128..383 ----
    float* X = (float*)(sm + SOFF_X);
    #pragma unroll
    for (int i = 0; i < 8; i++) {
        int row = wid + 8 * i;                 // warp handles rows wid, wid+8, ...
        int n = n0 + row;
        float4 a2 = make_float4(0.f, 0.f, 0.f, 0.f);
        float4 a3 = a2;
        float ebs = 0.f;
        if (n < NE) {
            int beg = g_offS[n], deg = g_histS[n];
            for (int e = beg; e < beg + deg; e++) {
                unsigned int ro = g_sRO[e];
                float w = g_sEb[e];
                int r = ro >> 17;
                int o = ro & 0x1FFFF;
                float4 rv = *(const float4*)&g_rel_rn[(long)r * IND + lane * 4];
                float4 ov = *(const float4*)&g_ent_rn[(long)o * IND + lane * 4];
                a2.x += w * rv.x; a2.y += w * rv.y; a2.z += w * rv.z; a2.w += w * rv.w;
                a3.x += w * ov.x; a3.y += w * ov.y; a3.z += w * ov.z; a3.w += w * ov.w;
                ebs += w;
            }
        }
        float inv = (ebs > 0.f) ? 1.f / ebs : 0.f;
        float4 p2 = make_float4(to_tf32(a2.x * inv), to_tf32(a2.y * inv),
                                to_tf32(a2.z * inv), to_tf32(a2.w * inv));
        float4 p3 = make_float4(to_tf32(a3.x * inv), to_tf32(a3.y * inv),
                                to_tf32(a3.z * inv), to_tf32(a3.w * inv));
        *(float4*)&X[row * XS + 128 + lane * 4] = p2;
        *(float4*)&X[row * XS + 256 + lane * 4] = p3;
        if (lane == 0) msk[row] = (inv > 0.f && n < NE) ? 1.f : 0.f;
    }

    // ---- phase 2: GEMM over 12 k-chunks ----
    float acc[13][4];
    #pragma unroll
    for (int t = 0; t < 13; t++)
        #pragma unroll
        for (int q = 0; q < 4; q++) acc[t][q] = 0.f;

    int wr = wid & 3;                          // warp row group (16 rows)
    int wc = wid >> 2;                         // warp col group (104 cols)
    int r0 = wr * 16 + (lane >> 2);
    int kk = lane & 3;
    int col0 = lane >> 2;
    const uint32_t* X32 = (const uint32_t*)X;

    for (int c = 0; c < 12; c++) {
        asm volatile("cp.async.wait_group 1;");
        __syncthreads();
        const uint32_t* B32 = (const uint32_t*)(sm + SOFF_B + (c & 1) * B_BUF_BYTES);
        #pragma unroll
        for (int s = 0; s < 4; s++) {
            uint32_t a[4];
            a[0] = X32[r0 * XS + c * 32 + s * 8 + kk];
            a[1] = X32[(r0 + 8) * XS + c * 32 + s * 8 + kk];
            a[2] = X32[r0 * XS + c * 32 + s * 8 + kk + 4];
            a[3] = X32[(r0 + 8) * XS + c * 32 + s * 8 + kk + 4];
            #pragma unroll
            for (int t = 0; t < 13; t++) {
                uint32_t b[2];
                b[0] = B32[(s * 8 + kk) * BP + wc * 104 + t * 8 + col0];
                b[1] = B32[(s * 8 + kk + 4) * BP + wc * 104 + t * 8 + col0];
                mma_tf32(acc[t], a, b);
            }
        }
        __syncthreads();
        if (c + 2 < 12) {
            uint32_t bbase = sb + SOFF_B + (c & 1) * B_BUF_BYTES;
            #pragma unroll
            for (int it = 0; it < 7; it++) {
                int idx = tid + it * 256;
                if (idx < B_F4_PER_CHUNK) {
                    int k = idx / 52, c4 = idx % 52;
                    uint32_t dst = bbase + (uint32_t)(k * (BP * 4) + c4 * 16);
                    const float* src = g_Wfull + (size_t)((c + 2) * 32 + k) * JP + c4 * 4;
                    asm volatile("cp.async.ca.shared.global [%0], [%1], 16;"
                                 :: "r"(dst), "l"(src));
                }
            }
            asm volatile("cp.async.commit_group;");
        } else {
            asm volatile("cp.async.commit_group;");   // keep group count in step
        }
    }

    // ---- epilogue ----
    int n_a = n0 + r0, n_b = n0 + r0 + 8;
    float ma = msk[r0], mb = msk[r0 + 8];
    #pragma unroll
    for (int t = 0; t < 13; t++) {
        int j = wc * 104 + t * 8 + 2 * (lane & 3);
        if (j >= OUTD) continue;
        float bj0 = bias[j], bj1 = bias[j + 1];
        if (n_a < NE) {
            float2 v;
            v.x = (ma > 0.f) ? fmaxf(acc[t][0] + bj0, 0.f) : 0.f;
            v.y = (ma > 0.f) ? fmaxf(acc[t][1] + bj1, 0.f) : 0.f;
            *(float2*)&out[(size_t)n_a * OUTD + j] = v;
        }
        if (n_b < NE) {
            float2 v;
            v.x = (mb > 0.f) ? fmaxf(acc[t][2] + bj0, 0.f) : 0.f;
            v.y = (mb > 0.f) ? fmaxf(acc[t][3] + bj1, 0.f) : 0.f;
            *(float2*)&out[(size_t)n_b * OUTD + j] = v;
        }
    }
}

// ---------------- h_rel ----------------
__global__ void kh(const float* __restrict__ ba, float* __restrict__ out) {
    __shared__ float s1[IND], s2[IND], rr[IND];
    int r = blockIdx.x, j = threadIdx.x;   // 200 threads
    if (j < IND) {
        s1[j] = g_S1[r * IND + j];
        s2[j] = g_S2[r * IND + j];
        rr[j] = g_rel_rn[r * IND + j];
    }
    __syncthreads();
    float ebr  = g_ebr[r];
    float icnt = 1.f / fmaxf((float)g_histR[r], 1.f);
    float acc = ebr * ba[j];
    #pragma unroll 4
    for (int c = 0; c < IND; c++) {
        acc += s1[c] * g_Wfull[c * JP + j];
        acc += (ebr * rr[c]) * g_Wfull[(IND + c) * JP + j];
        acc += s2[c] * g_Wfull[(2 * IND + c) * JP + j];
    }
    out[(long)NE * OUTD + r * OUTD + j] = fmaxf(acc * icnt, 0.f);
}

// ---------------- launch ----------------
extern "C" void kernel_launch(void* const* d_in, const int* in_sizes, int n_in,
                              void* d_out, int out_size) {
    const int*   trip = (const int*)d_in[0];
    const float* ent  = (const float*)d_in[1];
    const float* rel  = (const float*)d_in[2];
    const float* Wa   = (const float*)d_in[3];
    const float* ba   = (const float*)d_in[4];
    const float* Wa2  = (const float*)d_in[5];
    const float* ba2  = (const float*)d_in[6];
    float* out = (float*)d_out;

    cudaFuncSetAttribute(kfuse, cudaFuncAttributeMaxDynamicSharedMemorySize, SMEM_FUSE);

    kz<<<(NE + 255) / 256, 256>>>();
    kw<<<1, 512>>>(Wa, ba, Wa2, ba2);
    krn_rel<<<(NR * 32 + 255) / 256, 256>>>(rel);
    krn_ent<<<(NE * 32 + 255) / 256, 256>>>(ent);
    kwf<<<(KK * JP + 255) / 256, 256>>>(Wa);
    kedge<<<(EE + 255) / 256, 256>>>(trip);
    scanA<<<98, 1024>>>();
    scanBR<<<1, 32>>>();
    scanC<<<98, 1024>>>();
    kscatter<<<(EE + 255) / 256, 256>>>(trip);
    kr<<<dim3(NR, 8), 256>>>();
    kfuse<<<(NE + BM - 1) / BM, 256, SMEM_FUSE>>>(ba, out);
    kh<<<NR, OUTD>>>(ba, out);
}

// round 16
// speedup vs baseline: 1.0633x; 1.0633x over previous
#include <cuda_runtime.h>
#include <math.h>
#include <stdint.h>

#define NE   100000
#define NR   200
#define EE   500000
#define IND  128
#define OUTD 200
#define KK   384      // 128 ent_s | 128 P2(rel) | 128 P3(obj)
#define JP   208      // padded Wfull width

// ---------------- scratch ----------------
__device__ float g_ent_rn[NE * IND];
__device__ float g_rel_rn[NR * IND];
__device__ float g_P2[NE * IND];
__device__ float g_P3[NE * IND];
__device__ float g_inv[NE];
__device__ float g_d1[NE];
__device__ float g_d3[NE];
__device__ float g_d2[NR];
__device__ float g_weff[385];
__device__ float g_Wfull[KK * JP];        // [k][j], tf32-rounded, zero-padded j>=200
__device__ float g_eb[EE];
__device__ int   g_histS[NE];
__device__ int   g_offS[NE];
__device__ int   g_curS[NE];
__device__ int   g_histR[NR];
__device__ int   g_offR[NR];
__device__ int   g_curR[NR];
__device__ int   g_bsum[128];
__device__ int   g_boff[128];
__device__ uint2 g_sPack[EE];             // s-sorted: {(r<<17)|o, eb bits}
__device__ uint4 g_rPack[EE];             // r-sorted: {s, o, eb bits, 0}
__device__ float g_S1[NR * IND];
__device__ float g_S2[NR * IND];
__device__ float g_ebr[NR];

// ---------------- helpers ----------------
__device__ __forceinline__ uint32_t smem_u32(const void* p) {
    uint32_t a;
    asm("{ .reg .u64 t; cvta.to.shared.u64 t, %1; cvt.u32.u64 %0, t; }"
        : "=r"(a) : "l"(p));
    return a;
}
__device__ __forceinline__ float to_tf32(float x) {
    uint32_t u;
    asm("cvt.rna.tf32.f32 %0, %1;" : "=r"(u) : "f"(x));
    return __uint_as_float(u);
}
__device__ __forceinline__ void mma_tf32(float* c, const uint32_t* a, const uint32_t* b) {
    asm volatile(
        "mma.sync.aligned.m16n8k8.row.col.f32.tf32.tf32.f32 "
        "{%0,%1,%2,%3}, {%4,%5,%6,%7}, {%8,%9}, {%0,%1,%2,%3};"
        : "+f"(c[0]), "+f"(c[1]), "+f"(c[2]), "+f"(c[3])
        : "r"(a[0]), "r"(a[1]), "r"(a[2]), "r"(a[3]), "r"(b[0]), "r"(b[1]));
}
__device__ __forceinline__ float warp_sum(float v) {
    #pragma unroll
    for (int off = 16; off >= 1; off >>= 1) v += __shfl_xor_sync(0xffffffffu, v, off);
    return v;
}

// ---------------- zero small scratch ----------------
__global__ void kz() {
    int i = (int)blockIdx.x * blockDim.x + threadIdx.x;
    if (i < NE) g_histS[i] = 0;
    if (i < NR) { g_histR[i] = 0; g_ebr[i] = 0.f; }
    if (i < NR * IND) { g_S1[i] = 0.f; g_S2[i] = 0.f; }
}

// ---------------- w_eff = Wa2 @ Wa ; bias_eff ----------------
__global__ void kw(const float* __restrict__ Wa, const float* __restrict__ ba,
                   const float* __restrict__ Wa2, const float* __restrict__ ba2) {
    int k = threadIdx.x;
    if (k < 384) {
        float acc = 0.f;
        for (int j = 0; j < OUTD; j++) acc += Wa2[j] * Wa[j * 384 + k];
        g_weff[k] = acc;
    } else if (k == 384) {
        float acc = ba2[0];
        for (int j = 0; j < OUTD; j++) acc += Wa2[j] * ba[j];
        g_weff[384] = acc;
    }
}

// ---------------- renorm + per-row dots (tf32-rounded stores) ----------------
__global__ void krn_ent(const float* __restrict__ ent) {
    int w    = ((int)blockIdx.x * blockDim.x + threadIdx.x) >> 5;
    int lane = threadIdx.x & 31;
    if (w >= NE) return;
    float4 v = *(const float4*)&ent[(long)w * IND + lane * 4];
    float ss = warp_sum(v.x * v.x + v.y * v.y + v.z * v.z + v.w * v.w);
    float sc = fminf(1.f, 1.f / fmaxf(sqrtf(ss), 1e-12f));
    float4 r = make_float4(to_tf32(v.x * sc), to_tf32(v.y * sc),
                           to_tf32(v.z * sc), to_tf32(v.w * sc));
    *(float4*)&g_ent_rn[(long)w * IND + lane * 4] = r;
    float4 w1 = *(const float4*)&g_weff[lane * 4];
    float4 w3 = *(const float4*)&g_weff[256 + lane * 4];
    float a1 = warp_sum(r.x * w1.x + r.y * w1.y + r.z * w1.z + r.w * w1.w);
    float a3 = warp_sum(r.x * w3.x + r.y * w3.y + r.z * w3.z + r.w * w3.w);
    if (lane == 0) { g_d1[w] = a1; g_d3[w] = a3; }
}

__global__ void krn_rel(const float* __restrict__ rel) {
    int w    = ((int)blockIdx.x * blockDim.x + threadIdx.x) >> 5;
    int lane = threadIdx.x & 31;
    if (w >= NR) return;
    float4 v = *(const float4*)&rel[(long)w * IND + lane * 4];
    float ss = warp_sum(v.x * v.x + v.y * v.y + v.z * v.z + v.w * v.w);
    float sc = fminf(1.f, 1.f / fmaxf(sqrtf(ss), 1e-12f));
    float4 r = make_float4(to_tf32(v.x * sc), to_tf32(v.y * sc),
                           to_tf32(v.z * sc), to_tf32(v.w * sc));
    *(float4*)&g_rel_rn[(long)w * IND + lane * 4] = r;
    float4 w2 = *(const float4*)&g_weff[128 + lane * 4];
    float a2 = warp_sum(r.x * w2.x + r.y * w2.y + r.z * w2.z + r.w * w2.w);
    if (lane == 0) g_d2[w] = a2;
}

// ---------------- Wfull[384][208] = Wa^T, tf32-rounded, zero pad ----------------
__global__ void kwf(const float* __restrict__ Wa) {
    int idx = (int)blockIdx.x * blockDim.x + threadIdx.x;
    if (idx >= KK * JP) return;
    int k = idx / JP, j = idx % JP;
    g_Wfull[idx] = (j < OUTD) ? to_tf32(Wa[(long)j * KK + k]) : 0.f;
}

// ---------------- per-edge: e_b + histograms ----------------
__global__ void kedge(const int* __restrict__ trip) {
    int e = (int)blockIdx.x * blockDim.x + threadIdx.x;
    if (e >= EE) return;
    int s = trip[3 * e], r = trip[3 * e + 1], o = trip[3 * e + 2];
    float x  = g_d1[s] + g_d2[r] + g_d3[o] + g_weff[384];
    float lr = x >= 0.f ? x : 0.01f * x;
    float eb = expf(-lr);
    g_eb[e] = eb;
    atomicAdd(&g_histS[s], 1);
    atomicAdd(&g_histR[r], 1);
}

// ---------------- scans ----------------
__global__ void scanA() {
    __shared__ int sh[1024];
    int b = blockIdx.x, t = threadIdx.x;
    int i = b * 1024 + t;
    int v = (i < NE) ? g_histS[i] : 0;
    int x = v;
    sh[t] = x; __syncthreads();
    #pragma unroll
    for (int off = 1; off < 1024; off <<= 1) {
        int y = (t >= off) ? sh[t - off] : 0;
        __syncthreads();
        x += y; sh[t] = x;
        __syncthreads();
    }
    if (i < NE) g_offS[i] = x - v;
    if (t == 1023) g_bsum[b] = x;
}
__global__ void scanBR() {
    if (blockIdx.x == 0 && threadIdx.x == 0) {
        int acc = 0;
        for (int b = 0; b < 98; b++) { g_boff[b] = acc; acc += g_bsum[b]; }
    }
    if (blockIdx.x == 0 && threadIdx.x == 1) {
        int acc = 0;
        for (int r = 0; r < NR; r++) { g_offR[r] = acc; g_curR[r] = acc; acc += g_histR[r]; }
    }
}
__global__ void scanC() {
    int i = (int)blockIdx.x * blockDim.x + threadIdx.x;
    if (i < NE) {
        int o = g_offS[i] + g_boff[blockIdx.x];
        g_offS[i] = o;
        g_curS[i] = o;
    }
}

// ---------------- scatter edges by s and by r (packed stores) ----------------
__global__ void kscatter(const int* __restrict__ trip) {
    int e = (int)blockIdx.x * blockDim.x + threadIdx.x;
    if (e >= EE) return;
    int s = trip[3 * e], r = trip[3 * e + 1], o = trip[3 * e + 2];
    unsigned int ebb = __float_as_uint(g_eb[e]);
    int ps = atomicAdd(&g_curS[s], 1);
    g_sPack[ps] = make_uint2(((unsigned int)r << 17) | (unsigned int)o, ebb);
    int pr = atomicAdd(&g_curR[r], 1);
    g_rPack[pr] = make_uint4((unsigned int)s, (unsigned int)o, ebb, 0u);
}

// ---------------- warp-per-node: P2, P3, inv (tf32-rounded) ----------------
__global__ void knode() {
    int w    = ((int)blockIdx.x * blockDim.x + threadIdx.x) >> 5;
    int lane = threadIdx.x & 31;
    if (w >= NE) return;
    int beg = g_offS[w], deg = g_histS[w];
    float4 a2 = make_float4(0.f, 0.f, 0.f, 0.f);
    float4 a3 = a2;
    float ebs = 0.f;
    for (int i = beg; i < beg + deg; i++) {
        uint2 pk = g_sPack[i];
        float e = __uint_as_float(pk.y);
        int r = pk.x >> 17;
        int o = pk.x & 0x1FFFF;
        float4 rv = *(const float4*)&g_rel_rn[(long)r * IND + lane * 4];
        float4 ov = *(const float4*)&g_ent_rn[(long)o * IND + lane * 4];
        a2.x += e * rv.x; a2.y += e * rv.y; a2.z += e * rv.z; a2.w += e * rv.w;
        a3.x += e * ov.x; a3.y += e * ov.y; a3.z += e * ov.z; a3.w += e * ov.w;
        ebs += e;
    }
    float inv = (ebs > 0.f) ? 1.f / ebs : 0.f;
    float4 o2 = make_float4(to_tf32(a2.x * inv), to_tf32(a2.y * inv),
                            to_tf32(a2.z * inv), to_tf32(a2.w * inv));
    float4 o3 = make_float4(to_tf32(a3.x * inv), to_tf32(a3.y * inv),
                            to_tf32(a3.z * inv), to_tf32(a3.w * inv));
    *(float4*)&g_P2[(long)w * IND + lane * 4] = o2;
    *(float4*)&g_P3[(long)w * IND + lane * 4] = o3;
    if (lane == 0) g_inv[w] = inv;
}

// ---------------- relation sums ----------------
__global__ void kr() {
    int r = blockIdx.x;
    int chunk = blockIdx.y;
    int t = threadIdx.x;
    int d = t & 127;
    bool lo = t < 128;
    int base = g_offR[r], cnt = g_histR[r];
    int c0 = base + (int)((long)chunk * cnt / 8);
    int c1 = base + (int)((long)(chunk + 1) * cnt / 8);
    if (c1 <= c0) return;
    float acc = 0.f, ebsum = 0.f;
    #pragma unroll 4
    for (int i = c0; i < c1; i++) {
        uint4 p = g_rPack[i];
        float e = __uint_as_float(p.z);
        int node = lo ? (int)p.x : (int)p.y;
        acc += e * g_ent_rn[(long)node * IND + d];
        ebsum += e;
    }
    atomicAdd(lo ? &g_S1[r * IND + d] : &g_S2[r * IND + d], acc);
    if (t == 0) atomicAdd(&g_ebr[r], ebsum);
}

// ================= main GEMM via mma.sync tf32, full 208-col width =================
// BM=64: block = 64 rows x 208 cols = 4 row-groups x 2 col-groups of (16r x 104c)/warp.
// X read from DRAM exactly once (grid 1563); B re-reads hit L2 (Wfull = 320 KB).
#define BM   64
#define APAD 36
#define BP   216
#define A_BUF_BYTES (BM * APAD * 4)     // 9216
#define B_BUF_BYTES (32 * BP * 4)       // 27648
#define SOFF_A    1024
#define SOFF_B    (SOFF_A + 2 * A_BUF_BYTES)       // 19456
#define SMEM_MMA  (SOFF_B + 2 * B_BUF_BYTES)       // 74752
#define B_F4_PER_CHUNK (32 * 52)        // 1664 float4 per B chunk (full 208 cols)

__global__ void __launch_bounds__(256) kg2(const float* __restrict__ ba,
                                           float* __restrict__ out) {
    extern __shared__ __align__(128) char sm[];
    uint32_t sb = smem_u32(sm);
    float* bias = (float*)sm;               // 208 floats
    int tid = threadIdx.x, wid = tid >> 5, lane = tid & 31;
    int n0 = (int)blockIdx.x * BM;
    if (tid < JP) bias[tid] = (tid < OUTD) ? ba[tid] : 0.f;

    // ---- async chunk loader: A (64x32) + B (32x208) in one group ----
    auto issue = [&](int c, int buf) {
        const float* srcX = (c < 4) ? g_ent_rn : (c < 8) ? g_P2 : g_P3;
        int koff = (c & 3) * 32;
        uint32_t abase = sb + SOFF_A + buf * A_BUF_BYTES;
        #pragma unroll
        for (int it = 0; it < 2; it++) {
            int idx = tid + it * 256;            // 0..511 = 64 rows x 8 f4
            int row = idx >> 3, kq = idx & 7;
            int n = n0 + row;
            int nc = (n < NE) ? n : (NE - 1);
            uint32_t dst = abase + (uint32_t)(row * (APAD * 4) + kq * 16);
            const float* src = srcX + (size_t)nc * IND + koff + kq * 4;
            uint32_t sz = (n < NE) ? 16u : 0u;
            asm volatile("cp.async.ca.shared.global [%0], [%1], 16, %2;"
                         :: "r"(dst), "l"(src), "r"(sz));
        }
        uint32_t bbase = sb + SOFF_B + buf * B_BUF_BYTES;
        #pragma unroll
        for (int it = 0; it < 7; it++) {
            int idx = tid + it * 256;            // 0..1791, need 1664
            if (idx < B_F4_PER_CHUNK) {
                int k = idx / 52, c4 = idx % 52;
                uint32_t dst = bbase + (uint32_t)(k * (BP * 4) + c4 * 16);
                const float* src = g_Wfull + (size_t)(c * 32 + k) * JP + c4 * 4;
                asm volatile("cp.async.ca.shared.global [%0], [%1], 16;"
                             :: "r"(dst), "l"(src));
            }
        }
        asm volatile("cp.async.commit_group;");
    };

    float acc[13][4];
    #pragma unroll
    for (int t = 0; t < 13; t++)
        #pragma unroll
        for (int q = 0; q < 4; q++) acc[t][q] = 0.f;

    issue(0, 0);

    int wr = wid & 3;                           // row group (16 rows) -> rows 0..63
    int wc = wid >> 2;                          // col group (104 cols)
    int r0 = wr * 16 + (lane >> 2);
    int kk = lane & 3;
    int col0 = lane >> 2;

    for (int c = 0; c < 12; c++) {
        if (c < 11) issue(c + 1, (c + 1) & 1);
        if (c < 11) asm volatile("cp.async.wait_group 1;");
        else        asm volatile("cp.async.wait_group 0;");
        __syncthreads();
        const uint32_t* A32 = (const uint32_t*)(sm + SOFF_A + (c & 1) * A_BUF_BYTES);
        const uint32_t* B32 = (const uint32_t*)(sm + SOFF_B + (c & 1) * B_BUF_BYTES);
        #pragma unroll
        for (int s = 0; s < 4; s++) {
            uint32_t a[4];
            a[0] = A32[r0 * APAD + s * 8 + kk];
            a[1] = A32[(r0 + 8) * APAD + s * 8 + kk];
            a[2] = A32[r0 * APAD + s * 8 + kk + 4];
            a[3] = A32[(r0 + 8) * APAD + s * 8 + kk + 4];
            #pragma unroll
            for (int t = 0; t < 13; t++) {
                uint32_t b[2];
                b[0] = B32[(s * 8 + kk) * BP + wc * 104 + t * 8 + col0];
                b[1] = B32[(s * 8 + kk + 4) * BP + wc * 104 + t * 8 + col0];
                mma_tf32(acc[t], a, b);
            }
        }
        __syncthreads();
    }

    // ---- epilogue ----
    int n_a = n0 + r0, n_b = n0 + r0 + 8;
    float inva = (n_a < NE) ? g_inv[n_a] : 0.f;
    float invb = (n_b < NE) ? g_inv[n_b] : 0.f;
    #pragma unroll
    for (int t = 0; t < 13; t++) {
        int j = wc * 104 + t * 8 + 2 * (lane & 3);
        if (j >= OUTD) continue;
        float bj0 = bias[j], bj1 = bias[j + 1];
        if (n_a < NE) {
            float2 v;
            v.x = (inva > 0.f) ? fmaxf(acc[t][0] + bj0, 0.f) : 0.f;
            v.y = (inva > 0.f) ? fmaxf(acc[t][1] + bj1, 0.f) : 0.f;
            *(float2*)&out[(size_t)n_a * OUTD + j] = v;
        }
        if (n_b < NE) {
            float2 v;
            v.x = (invb > 0.f) ? fmaxf(acc[t][2] + bj0, 0.f) : 0.f;
            v.y = (invb > 0.f) ? fmaxf(acc[t][3] + bj1, 0.f) : 0.f;
            *(float2*)&out[(size_t)n_b * OUTD + j] = v;
        }
    }
}

// ---------------- h_rel ----------------
__global__ void kh(const float* __restrict__ ba, float* __restrict__ out) {
    __shared__ float s1[IND], s2[IND], rr[IND];
    int r = blockIdx.x, j = threadIdx.x;   // 200 threads
    if (j < IND) {
        s1[j] = g_S1[r * IND + j];
        s2[j] = g_S2[r * IND + j];
        rr[j] = g_rel_rn[r * IND + j];
    }
    __syncthreads();
    float ebr  = g_ebr[r];
    float icnt = 1.f / fmaxf((float)g_histR[r], 1.f);
    float acc = ebr * ba[j];
    #pragma unroll 4
    for (int c = 0; c < IND; c++) {
        acc += s1[c] * g_Wfull[c * JP + j];
        acc += (ebr * rr[c]) * g_Wfull[(IND + c) * JP + j];
        acc += s2[c] * g_Wfull[(2 * IND + c) * JP + j];
    }
    out[(long)NE * OUTD + r * OUTD + j] = fmaxf(acc * icnt, 0.f);
}

// ---------------- launch ----------------
extern "C" void kernel_launch(void* const* d_in, const int* in_sizes, int n_in,
                              void* d_out, int out_size) {
    const int*   trip = (const int*)d_in[0];
    const float* ent  = (const float*)d_in[1];
    const float* rel  = (const float*)d_in[2];
    const float* Wa   = (const float*)d_in[3];
    const float* ba   = (const float*)d_in[4];
    const float* Wa2  = (const float*)d_in[5];
    const float* ba2  = (const float*)d_in[6];
    float* out = (float*)d_out;

    cudaFuncSetAttribute(kg2, cudaFuncAttributeMaxDynamicSharedMemorySize, SMEM_MMA);

    kz<<<(NE + 255) / 256, 256>>>();
    kw<<<1, 512>>>(Wa, ba, Wa2, ba2);
    krn_rel<<<(NR * 32 + 255) / 256, 256>>>(rel);
    krn_ent<<<(NE * 32 + 255) / 256, 256>>>(ent);
    kwf<<<(KK * JP + 255) / 256, 256>>>(Wa);
    kedge<<<(EE + 255) / 256, 256>>>(trip);
    scanA<<<98, 1024>>>();
    scanBR<<<1, 32>>>();
    scanC<<<98, 1024>>>();
    kscatter<<<(EE + 255) / 256, 256>>>(trip);
    knode<<<(NE * 32 + 255) / 256, 256>>>();
    kr<<<dim3(NR, 8), 256>>>();
    kg2<<<(NE + BM - 1) / BM, 256, SMEM_MMA>>>(ba, out);
    kh<<<NR, OUTD>>>(ba, out);
}